// round 1
// baseline (speedup 1.0000x reference)
#include <cuda_runtime.h>
#include <cstdint>

#define N_PEP 20000
#define N_MHC 5000
#define N_TCR 100000
#define EMB 128
#define HID 256
#define E_PM 200000
#define E_MT 400000
#define BATCH 50000

// ---------------- scratch (device globals; no allocation allowed) ----------------
__device__ float g_mean_pm[N_MHC * EMB];
__device__ float g_mean_mt1[N_TCR * EMB];
__device__ float g_mean_mt2[N_TCR * HID];
__device__ float g_mhc1[N_MHC * HID];
__device__ float g_mhc2[N_MHC * HID];
__device__ float g_tcr1[N_TCR * HID];
__device__ float g_tcr2[N_TCR * HID];
__device__ float g_cp[N_PEP * HID];
__device__ float g_cm[N_MHC * HID];
__device__ float g_ct[BATCH * HID];
__device__ float g_Mp[HID * EMB];
__device__ float g_bp[HID];
__device__ int g_head_pm[N_MHC];
__device__ int g_next_pm[E_PM];
__device__ int g_head_mt[N_TCR];
__device__ int g_next_mt[E_MT];

static inline int divup(int a, int b) { return (a + b - 1) / b; }

// ---------------- edge list -> per-dst linked lists ----------------
__global__ void init_heads_kernel(int* head_pm, int* head_mt) {
    int i = blockIdx.x * blockDim.x + threadIdx.x;
    if (i < N_MHC) head_pm[i] = -1;
    if (i < N_TCR) head_mt[i] = -1;
}

__global__ void build_edges_kernel(const int* __restrict__ dst, int* head, int* next, int E) {
    int e = blockIdx.x * blockDim.x + threadIdx.x;
    if (e < E) next[e] = atomicExch(&head[dst[e]], e);
}

// ---------------- mean aggregation: warp per dst node ----------------
template <int K>
__global__ void agg_kernel(const int* __restrict__ head, const int* __restrict__ next,
                           const int* __restrict__ srcArr, const float* __restrict__ feat,
                           float* __restrict__ outMean, int nNodes) {
    int w = (blockIdx.x * blockDim.x + threadIdx.x) >> 5;
    int lane = threadIdx.x & 31;
    if (w >= nNodes) return;
    constexpr int NV = K / 128;  // float4 per lane
    float4 acc[NV];
#pragma unroll
    for (int v = 0; v < NV; v++) acc[v] = make_float4(0.f, 0.f, 0.f, 0.f);
    int e = head[w];
    int cnt = 0;
    while (e >= 0) {
        int en = __ldg(&next[e]);
        int s = __ldg(&srcArr[e]);
        const float4* fr = (const float4*)(feat + (size_t)s * K);
#pragma unroll
        for (int v = 0; v < NV; v++) {
            float4 f = __ldg(&fr[lane + v * 32]);
            acc[v].x += f.x; acc[v].y += f.y; acc[v].z += f.z; acc[v].w += f.w;
        }
        cnt++;
        e = en;
    }
    float inv = 1.0f / (float)(cnt > 1 ? cnt : 1);
    float4* o = (float4*)(outMean + (size_t)w * K);
#pragma unroll
    for (int v = 0; v < NV; v++)
        o[lane + v * 32] = make_float4(acc[v].x * inv, acc[v].y * inv, acc[v].z * inv, acc[v].w * inv);
}

// ---------------- fused GEMM: Y = relu?(A@Wa^T (+ B@Wb^T) + bias) ----------------
// A: [rows, Ka] (optionally gathered via rowidx), Wa: [N, *] with leading dim ldwa, col offset offa
// block tile 128x128, 256 threads, 8x8 micro-tile, BK=32, XOR-swizzled smem
__global__ __launch_bounds__(256, 2) void gemm_kernel(
    const float* __restrict__ A, int Ka, const float* __restrict__ Wa, int ldwa, int offa,
    const float* __restrict__ B, int Kb, const float* __restrict__ Wb, int ldwb, int offb,
    const float* __restrict__ bias, const int* __restrict__ rowidx,
    float* __restrict__ Y, int rows, int N, int do_relu) {
    __shared__ __align__(16) float As[32][128];
    __shared__ __align__(16) float Ws[32][128];
    const int t = threadIdx.x;
    const int m0 = blockIdx.x * 128;
    const int n0 = blockIdx.y * 128;
    const int tx = t & 15;   // 16 cols of threads * 8  = 128 n
    const int ty = t >> 4;   // 16 rows of threads * 8  = 128 m
    float acc[8][8];
#pragma unroll
    for (int i = 0; i < 8; i++)
#pragma unroll
        for (int j = 0; j < 8; j++) acc[i][j] = 0.f;

    for (int pass = 0; pass < 2; pass++) {
        const float* X = pass ? B : A;
        if (X == nullptr) continue;
        const float* W = pass ? Wb : Wa;
        const int K = pass ? Kb : Ka;
        const int ldw = pass ? ldwb : ldwa;
        const int off = pass ? offb : offa;
        for (int k0 = 0; k0 < K; k0 += 32) {
            __syncthreads();
#pragma unroll
            for (int it = 0; it < 4; it++) {
                int L = it * 256 + t;
                int m = L >> 3;          // 0..127
                int kq = (L & 7) * 4;    // 0,4,...,28
                int sw = kq;             // swizzle constant (kq & 28 == kq)
                // X tile
                float4 v = make_float4(0.f, 0.f, 0.f, 0.f);
                int row = m0 + m;
                if (row < rows) {
                    int r = rowidx ? __ldg(&rowidx[row]) : row;
                    v = *(const float4*)&X[(size_t)r * K + k0 + kq];
                }
                As[kq + 0][m ^ sw] = v.x;
                As[kq + 1][m ^ sw] = v.y;
                As[kq + 2][m ^ sw] = v.z;
                As[kq + 3][m ^ sw] = v.w;
                // W tile (n plays the role of m)
                float4 w4 = make_float4(0.f, 0.f, 0.f, 0.f);
                int n = n0 + m;
                if (n < N) w4 = *(const float4*)&W[(size_t)n * ldw + off + k0 + kq];
                Ws[kq + 0][m ^ sw] = w4.x;
                Ws[kq + 1][m ^ sw] = w4.y;
                Ws[kq + 2][m ^ sw] = w4.z;
                Ws[kq + 3][m ^ sw] = w4.w;
            }
            __syncthreads();
#pragma unroll
            for (int kk = 0; kk < 32; kk++) {
                const int sw = kk & 28;
                float a[8], b[8];
                *(float4*)&a[0] = *(const float4*)&As[kk][(ty * 8) ^ sw];
                *(float4*)&a[4] = *(const float4*)&As[kk][(ty * 8 + 4) ^ sw];
                *(float4*)&b[0] = *(const float4*)&Ws[kk][(tx * 8) ^ sw];
                *(float4*)&b[4] = *(const float4*)&Ws[kk][(tx * 8 + 4) ^ sw];
#pragma unroll
                for (int i = 0; i < 8; i++)
#pragma unroll
                    for (int j = 0; j < 8; j++) acc[i][j] = fmaf(a[i], b[j], acc[i][j]);
            }
        }
    }
    // epilogue
    float bs[8];
    if (bias) {
        *(float4*)&bs[0] = *(const float4*)&bias[n0 + tx * 8];
        *(float4*)&bs[4] = *(const float4*)&bias[n0 + tx * 8 + 4];
    } else {
#pragma unroll
        for (int j = 0; j < 8; j++) bs[j] = 0.f;
    }
#pragma unroll
    for (int i = 0; i < 8; i++) {
        int row = m0 + ty * 8 + i;
        if (row >= rows) continue;
        float o[8];
#pragma unroll
        for (int j = 0; j < 8; j++) {
            float v = acc[i][j] + bs[j];
            o[j] = do_relu ? fmaxf(v, 0.f) : v;
        }
        float* yp = &Y[(size_t)row * N + n0 + tx * 8];
        *(float4*)&yp[0] = *(float4*)&o[0];
        *(float4*)&yp[4] = *(float4*)&o[4];
    }
}

// ---------------- head folding precompute: Mp = W1p @ proj_W, bp = W1p @ proj_b + head_b1 ----------------
__global__ void prep_head_kernel(const float* __restrict__ head_W1, const float* __restrict__ head_b1,
                                 const float* __restrict__ proj_W, const float* __restrict__ proj_b,
                                 float* __restrict__ Mp, float* __restrict__ bp) {
    int n = blockIdx.x;       // 0..255
    int k = threadIdx.x;      // 0..127
    float acc = 0.f;
    for (int j = 0; j < HID; j++) {
        float w = __ldg(&head_W1[n * (3 * HID) + j]);   // W1p[n, j]
        acc = fmaf(w, __ldg(&proj_W[j * EMB + k]), acc);
    }
    Mp[n * EMB + k] = acc;
    // bias: each thread covers j = k and j = k+128
    float pb = __ldg(&head_W1[n * (3 * HID) + k]) * __ldg(&proj_b[k]) +
               __ldg(&head_W1[n * (3 * HID) + k + 128]) * __ldg(&proj_b[k + 128]);
    __shared__ float s[128];
    s[k] = pb;
    __syncthreads();
    for (int st = 64; st > 0; st >>= 1) {
        if (k < st) s[k] += s[k + st];
        __syncthreads();
    }
    if (k == 0) bp[n] = s[0] + head_b1[n];
}

// ---------------- final: logit = w2 . relu(cp[p] + cm[m] + ct[b]) + b2 ----------------
__global__ void final_kernel(const int* __restrict__ pp, const int* __restrict__ pm,
                             const float* __restrict__ cp, const float* __restrict__ cm,
                             const float* __restrict__ ct, const float* __restrict__ w2,
                             const float* __restrict__ b2, float* __restrict__ out, int Bn) {
    int w = (blockIdx.x * blockDim.x + threadIdx.x) >> 5;
    int lane = threadIdx.x & 31;
    if (w >= Bn) return;
    int ip = __ldg(&pp[w]);
    int im = __ldg(&pm[w]);
    const float4* rp = (const float4*)(cp + (size_t)ip * HID);
    const float4* rm = (const float4*)(cm + (size_t)im * HID);
    const float4* rt = (const float4*)(ct + (size_t)w * HID);
    const float4* rw = (const float4*)w2;
    float sum = 0.f;
#pragma unroll
    for (int v = 0; v < 2; v++) {
        float4 a = __ldg(&rp[lane + v * 32]);
        float4 b = __ldg(&rm[lane + v * 32]);
        float4 c = __ldg(&rt[lane + v * 32]);
        float4 ww = __ldg(&rw[lane + v * 32]);
        sum = fmaf(fmaxf(a.x + b.x + c.x, 0.f), ww.x, sum);
        sum = fmaf(fmaxf(a.y + b.y + c.y, 0.f), ww.y, sum);
        sum = fmaf(fmaxf(a.z + b.z + c.z, 0.f), ww.z, sum);
        sum = fmaf(fmaxf(a.w + b.w + c.w, 0.f), ww.w, sum);
    }
#pragma unroll
    for (int o = 16; o > 0; o >>= 1) sum += __shfl_xor_sync(0xFFFFFFFFu, sum, o);
    if (lane == 0) out[w] = sum + b2[0];
}

// ---------------- launch ----------------
static void launch_gemm(const float* A, int Ka, const float* Wa, int ldwa, int offa,
                        const float* B, int Kb, const float* Wb, int ldwb, int offb,
                        const float* bias, const int* rowidx, float* Y, int rows, int relu) {
    dim3 grid(divup(rows, 128), HID / 128);
    gemm_kernel<<<grid, 256>>>(A, Ka, Wa, ldwa, offa, B, Kb, Wb, ldwb, offb, bias, rowidx, Y,
                               rows, HID, relu);
}

extern "C" void kernel_launch(void* const* d_in, const int* in_sizes, int n_in,
                              void* d_out, int out_size) {
    const float* emb_pep = (const float*)d_in[0];
    const float* emb_mhc = (const float*)d_in[1];
    const float* emb_tcr = (const float*)d_in[2];
    const int* src_pm = (const int*)d_in[3];
    const int* dst_pm = (const int*)d_in[4];
    const int* src_mt = (const int*)d_in[5];
    const int* dst_mt = (const int*)d_in[6];
    const int* pack_pep = (const int*)d_in[7];
    const int* pack_mhc = (const int*)d_in[8];
    const int* pack_tcr = (const int*)d_in[9];
    const float* l1_pm_Wl = (const float*)d_in[10];
    const float* l1_pm_bl = (const float*)d_in[11];
    const float* l1_pm_Wr = (const float*)d_in[12];
    const float* l1_mt_Wl = (const float*)d_in[13];
    const float* l1_mt_bl = (const float*)d_in[14];
    const float* l1_mt_Wr = (const float*)d_in[15];
    const float* l2_pm_Wl = (const float*)d_in[16];
    const float* l2_pm_bl = (const float*)d_in[17];
    const float* l2_pm_Wr = (const float*)d_in[18];
    const float* l2_mt_Wl = (const float*)d_in[19];
    const float* l2_mt_bl = (const float*)d_in[20];
    const float* l2_mt_Wr = (const float*)d_in[21];
    const float* proj_W = (const float*)d_in[22];
    const float* proj_b = (const float*)d_in[23];
    const float* head_W1 = (const float*)d_in[24];
    const float* head_b1 = (const float*)d_in[25];
    const float* head_W2 = (const float*)d_in[26];
    const float* head_b2 = (const float*)d_in[27];
    float* out = (float*)d_out;

    float *mean_pm, *mean_mt1, *mean_mt2, *mhc1, *mhc2, *tcr1, *tcr2, *cp, *cm, *ct, *Mp, *bp;
    int *head_pm, *next_pm, *head_mt, *next_mt;
    cudaGetSymbolAddress((void**)&mean_pm, g_mean_pm);
    cudaGetSymbolAddress((void**)&mean_mt1, g_mean_mt1);
    cudaGetSymbolAddress((void**)&mean_mt2, g_mean_mt2);
    cudaGetSymbolAddress((void**)&mhc1, g_mhc1);
    cudaGetSymbolAddress((void**)&mhc2, g_mhc2);
    cudaGetSymbolAddress((void**)&tcr1, g_tcr1);
    cudaGetSymbolAddress((void**)&tcr2, g_tcr2);
    cudaGetSymbolAddress((void**)&cp, g_cp);
    cudaGetSymbolAddress((void**)&cm, g_cm);
    cudaGetSymbolAddress((void**)&ct, g_ct);
    cudaGetSymbolAddress((void**)&Mp, g_Mp);
    cudaGetSymbolAddress((void**)&bp, g_bp);
    cudaGetSymbolAddress((void**)&head_pm, g_head_pm);
    cudaGetSymbolAddress((void**)&next_pm, g_next_pm);
    cudaGetSymbolAddress((void**)&head_mt, g_head_mt);
    cudaGetSymbolAddress((void**)&next_mt, g_next_mt);

    // 1) linked-list build
    init_heads_kernel<<<divup(N_TCR, 256), 256>>>(head_pm, head_mt);
    build_edges_kernel<<<divup(E_PM, 256), 256>>>(dst_pm, head_pm, next_pm, E_PM);
    build_edges_kernel<<<divup(E_MT, 256), 256>>>(dst_mt, head_mt, next_mt, E_MT);

    // 2) layer-1 aggregations (mean_pm is shared with layer 2)
    agg_kernel<EMB><<<divup(N_MHC, 8), 256>>>(head_pm, next_pm, src_pm, emb_pep, mean_pm, N_MHC);
    agg_kernel<EMB><<<divup(N_TCR, 8), 256>>>(head_mt, next_mt, src_mt, emb_mhc, mean_mt1, N_TCR);

    // 3) layer-1 SAGE GEMMs
    launch_gemm(mean_pm, EMB, l1_pm_Wl, EMB, 0, emb_mhc, EMB, l1_pm_Wr, EMB, 0,
                l1_pm_bl, nullptr, mhc1, N_MHC, 1);
    launch_gemm(mean_mt1, EMB, l1_mt_Wl, EMB, 0, emb_tcr, EMB, l1_mt_Wr, EMB, 0,
                l1_mt_bl, nullptr, tcr1, N_TCR, 1);

    // 4) layer-2 aggregation over mhc1
    agg_kernel<HID><<<divup(N_TCR, 8), 256>>>(head_mt, next_mt, src_mt, mhc1, mean_mt2, N_TCR);

    // 5) layer-2 SAGE GEMMs
    launch_gemm(mean_pm, EMB, l2_pm_Wl, EMB, 0, mhc1, HID, l2_pm_Wr, HID, 0,
                l2_pm_bl, nullptr, mhc2, N_MHC, 1);
    launch_gemm(mean_mt2, HID, l2_mt_Wl, HID, 0, tcr1, HID, l2_mt_Wr, HID, 0,
                l2_mt_bl, nullptr, tcr2, N_TCR, 1);

    // 6) head contributions
    prep_head_kernel<<<HID, 128>>>(head_W1, head_b1, proj_W, proj_b, Mp, bp);
    launch_gemm(emb_pep, EMB, Mp, EMB, 0, nullptr, 0, nullptr, 0, 0, bp, nullptr, cp, N_PEP, 0);
    launch_gemm(mhc2, HID, head_W1, 3 * HID, HID, nullptr, 0, nullptr, 0, 0,
                nullptr, nullptr, cm, N_MHC, 0);
    launch_gemm(tcr2, HID, head_W1, 3 * HID, 2 * HID, nullptr, 0, nullptr, 0, 0,
                nullptr, pack_tcr, ct, BATCH, 0);

    // 7) final dot
    final_kernel<<<divup(BATCH, 8), 256>>>(pack_pep, pack_mhc, cp, cm, ct, head_W2, head_b2,
                                           out, BATCH);
}

// round 2
// speedup vs baseline: 1.6422x; 1.6422x over previous
#include <cuda_runtime.h>
#include <cstdint>

#define N_PEP 20000
#define N_MHC 5000
#define N_TCR 100000
#define EMB 128
#define HID 256
#define E_PM 200000
#define E_MT 400000
#define BATCH 50000
#define MAXD 50000   // max distinct tcr nodes = min(N_TCR, BATCH)

// ---------------- scratch (device globals; no allocation allowed) ----------------
__device__ float g_mean_pm[N_MHC * EMB];
__device__ float g_mhc1[N_MHC * HID];
__device__ float g_mhc2[N_MHC * HID];
__device__ float g_cm[N_MHC * HID];
__device__ float g_cp[N_PEP * HID];
__device__ float g_Mp[HID * EMB];
__device__ float g_bp[HID];
// compacted tcr pipeline
__device__ float g_mean_mt1c[MAXD * EMB];
__device__ float g_mean_mt2c[MAXD * HID];
__device__ float g_tcr1c[MAXD * HID];
__device__ float g_tcr2c[MAXD * HID];
__device__ float g_ctc[MAXD * HID];
__device__ int g_map[N_TCR];    // tcr node -> compact row (-1 if unused)
__device__ int g_list[MAXD];    // compact row -> tcr node
__device__ int g_cnt[1];
// edge linked lists
__device__ int g_head_pm[N_MHC];
__device__ int g_next_pm[E_PM];
__device__ int g_head_mt[N_TCR];
__device__ int g_next_mt[E_MT];

static inline int divup(int a, int b) { return (a + b - 1) / b; }

// ---------------- init: heads, map, counter ----------------
__global__ void init_kernel(int* head_pm, int* head_mt, int* map, int* cnt) {
    int i = blockIdx.x * blockDim.x + threadIdx.x;
    if (i == 0) cnt[0] = 0;
    if (i < N_MHC) head_pm[i] = -1;
    if (i < N_TCR) { head_mt[i] = -1; map[i] = -1; }
}

__global__ void build_edges_kernel(const int* __restrict__ dst, int* head, int* next, int E) {
    int e = blockIdx.x * blockDim.x + threadIdx.x;
    if (e < E) next[e] = atomicExch(&head[dst[e]], e);
}

// ---------------- dedup pack_tcr ----------------
__global__ void mark_kernel(const int* __restrict__ pack, int* map, int B) {
    int i = blockIdx.x * blockDim.x + threadIdx.x;
    if (i < B) map[pack[i]] = -2;   // mark present (races benign: same value)
}

__global__ void compact_kernel(int* map, int* list, int* cnt) {
    int i = blockIdx.x * blockDim.x + threadIdx.x;
    if (i < N_TCR && map[i] == -2) {
        int idx = atomicAdd(cnt, 1);
        list[idx] = i;
        map[i] = idx;
    }
}

// ---------------- mean aggregation (full nodes): warp per dst node ----------------
template <int K>
__global__ void agg_kernel(const int* __restrict__ head, const int* __restrict__ next,
                           const int* __restrict__ srcArr, const float* __restrict__ feat,
                           float* __restrict__ outMean, int nNodes) {
    int w = (blockIdx.x * blockDim.x + threadIdx.x) >> 5;
    int lane = threadIdx.x & 31;
    if (w >= nNodes) return;
    constexpr int NV = K / 128;
    float4 acc[NV];
#pragma unroll
    for (int v = 0; v < NV; v++) acc[v] = make_float4(0.f, 0.f, 0.f, 0.f);
    int e = head[w];
    int cnt = 0;
    while (e >= 0) {
        int en = __ldg(&next[e]);
        int s = __ldg(&srcArr[e]);
        const float4* fr = (const float4*)(feat + (size_t)s * K);
#pragma unroll
        for (int v = 0; v < NV; v++) {
            float4 f = __ldg(&fr[lane + v * 32]);
            acc[v].x += f.x; acc[v].y += f.y; acc[v].z += f.z; acc[v].w += f.w;
        }
        cnt++;
        e = en;
    }
    float inv = 1.0f / (float)(cnt > 1 ? cnt : 1);
    float4* o = (float4*)(outMean + (size_t)w * K);
#pragma unroll
    for (int v = 0; v < NV; v++)
        o[lane + v * 32] = make_float4(acc[v].x * inv, acc[v].y * inv, acc[v].z * inv, acc[v].w * inv);
}

// ---------------- mean aggregation over compacted node list ----------------
template <int K>
__global__ void agg_compact_kernel(const int* __restrict__ head, const int* __restrict__ next,
                                   const int* __restrict__ srcArr, const float* __restrict__ feat,
                                   float* __restrict__ outMean, const int* __restrict__ list,
                                   const int* __restrict__ cntp) {
    int w = (blockIdx.x * blockDim.x + threadIdx.x) >> 5;
    int lane = threadIdx.x & 31;
    if (w >= __ldg(cntp)) return;
    int node = __ldg(&list[w]);
    constexpr int NV = K / 128;
    float4 acc[NV];
#pragma unroll
    for (int v = 0; v < NV; v++) acc[v] = make_float4(0.f, 0.f, 0.f, 0.f);
    int e = head[node];
    int cnt = 0;
    while (e >= 0) {
        int en = __ldg(&next[e]);
        int s = __ldg(&srcArr[e]);
        const float4* fr = (const float4*)(feat + (size_t)s * K);
#pragma unroll
        for (int v = 0; v < NV; v++) {
            float4 f = __ldg(&fr[lane + v * 32]);
            acc[v].x += f.x; acc[v].y += f.y; acc[v].z += f.z; acc[v].w += f.w;
        }
        cnt++;
        e = en;
    }
    float inv = 1.0f / (float)(cnt > 1 ? cnt : 1);
    float4* o = (float4*)(outMean + (size_t)w * K);
#pragma unroll
    for (int v = 0; v < NV; v++)
        o[lane + v * 32] = make_float4(acc[v].x * inv, acc[v].y * inv, acc[v].z * inv, acc[v].w * inv);
}

// ---------------- fused GEMM: Y = relu?(A@Wa^T (+ B@Wb^T) + bias) ----------------
// rows can be overridden at runtime via rows_ptr (for compacted pipelines).
// rowidx_a / rowidx_b gather rows of A / B respectively.
__global__ __launch_bounds__(256, 2) void gemm_kernel(
    const float* __restrict__ A, int Ka, const float* __restrict__ Wa, int ldwa, int offa,
    const float* __restrict__ B, int Kb, const float* __restrict__ Wb, int ldwb, int offb,
    const float* __restrict__ bias, const int* __restrict__ rowidx_a,
    const int* __restrict__ rowidx_b, const int* __restrict__ rows_ptr,
    float* __restrict__ Y, int rows, int N, int do_relu) {
    if (rows_ptr) {
        int r = __ldg(rows_ptr);
        rows = r < rows ? r : rows;
    }
    const int m0 = blockIdx.x * 128;
    if (m0 >= rows) return;
    __shared__ __align__(16) float As[32][128];
    __shared__ __align__(16) float Ws[32][128];
    const int t = threadIdx.x;
    const int n0 = blockIdx.y * 128;
    const int tx = t & 15;
    const int ty = t >> 4;
    float acc[8][8];
#pragma unroll
    for (int i = 0; i < 8; i++)
#pragma unroll
        for (int j = 0; j < 8; j++) acc[i][j] = 0.f;

    for (int pass = 0; pass < 2; pass++) {
        const float* X = pass ? B : A;
        if (X == nullptr) continue;
        const float* W = pass ? Wb : Wa;
        const int K = pass ? Kb : Ka;
        const int ldw = pass ? ldwb : ldwa;
        const int off = pass ? offb : offa;
        const int* ridx = pass ? rowidx_b : rowidx_a;
        for (int k0 = 0; k0 < K; k0 += 32) {
            __syncthreads();
#pragma unroll
            for (int it = 0; it < 4; it++) {
                int L = it * 256 + t;
                int m = L >> 3;
                int kq = (L & 7) * 4;
                int sw = kq;
                float4 v = make_float4(0.f, 0.f, 0.f, 0.f);
                int row = m0 + m;
                if (row < rows) {
                    int r = ridx ? __ldg(&ridx[row]) : row;
                    v = *(const float4*)&X[(size_t)r * K + k0 + kq];
                }
                As[kq + 0][m ^ sw] = v.x;
                As[kq + 1][m ^ sw] = v.y;
                As[kq + 2][m ^ sw] = v.z;
                As[kq + 3][m ^ sw] = v.w;
                float4 w4 = make_float4(0.f, 0.f, 0.f, 0.f);
                int n = n0 + m;
                if (n < N) w4 = *(const float4*)&W[(size_t)n * ldw + off + k0 + kq];
                Ws[kq + 0][m ^ sw] = w4.x;
                Ws[kq + 1][m ^ sw] = w4.y;
                Ws[kq + 2][m ^ sw] = w4.z;
                Ws[kq + 3][m ^ sw] = w4.w;
            }
            __syncthreads();
#pragma unroll
            for (int kk = 0; kk < 32; kk++) {
                const int sw = kk & 28;
                float a[8], b[8];
                *(float4*)&a[0] = *(const float4*)&As[kk][(ty * 8) ^ sw];
                *(float4*)&a[4] = *(const float4*)&As[kk][(ty * 8 + 4) ^ sw];
                *(float4*)&b[0] = *(const float4*)&Ws[kk][(tx * 8) ^ sw];
                *(float4*)&b[4] = *(const float4*)&Ws[kk][(tx * 8 + 4) ^ sw];
#pragma unroll
                for (int i = 0; i < 8; i++)
#pragma unroll
                    for (int j = 0; j < 8; j++) acc[i][j] = fmaf(a[i], b[j], acc[i][j]);
            }
        }
    }
    float bs[8];
    if (bias) {
        *(float4*)&bs[0] = *(const float4*)&bias[n0 + tx * 8];
        *(float4*)&bs[4] = *(const float4*)&bias[n0 + tx * 8 + 4];
    } else {
#pragma unroll
        for (int j = 0; j < 8; j++) bs[j] = 0.f;
    }
#pragma unroll
    for (int i = 0; i < 8; i++) {
        int row = m0 + ty * 8 + i;
        if (row >= rows) continue;
        float o[8];
#pragma unroll
        for (int j = 0; j < 8; j++) {
            float v = acc[i][j] + bs[j];
            o[j] = do_relu ? fmaxf(v, 0.f) : v;
        }
        float* yp = &Y[(size_t)row * N + n0 + tx * 8];
        *(float4*)&yp[0] = *(float4*)&o[0];
        *(float4*)&yp[4] = *(float4*)&o[4];
    }
}

// ---------------- head folding precompute ----------------
__global__ void prep_head_kernel(const float* __restrict__ head_W1, const float* __restrict__ head_b1,
                                 const float* __restrict__ proj_W, const float* __restrict__ proj_b,
                                 float* __restrict__ Mp, float* __restrict__ bp) {
    int n = blockIdx.x;
    int k = threadIdx.x;
    float acc = 0.f;
    for (int j = 0; j < HID; j++) {
        float w = __ldg(&head_W1[n * (3 * HID) + j]);
        acc = fmaf(w, __ldg(&proj_W[j * EMB + k]), acc);
    }
    Mp[n * EMB + k] = acc;
    float pb = __ldg(&head_W1[n * (3 * HID) + k]) * __ldg(&proj_b[k]) +
               __ldg(&head_W1[n * (3 * HID) + k + 128]) * __ldg(&proj_b[k + 128]);
    __shared__ float s[128];
    s[k] = pb;
    __syncthreads();
    for (int st = 64; st > 0; st >>= 1) {
        if (k < st) s[k] += s[k + st];
        __syncthreads();
    }
    if (k == 0) bp[n] = s[0] + head_b1[n];
}

// ---------------- final: logit = w2 . relu(cp[p] + cm[m] + ctc[map[t]]) + b2 ----------------
__global__ void final_kernel(const int* __restrict__ pp, const int* __restrict__ pm,
                             const int* __restrict__ pt, const int* __restrict__ map,
                             const float* __restrict__ cp, const float* __restrict__ cm,
                             const float* __restrict__ ctc, const float* __restrict__ w2,
                             const float* __restrict__ b2, float* __restrict__ out, int Bn) {
    int w = (blockIdx.x * blockDim.x + threadIdx.x) >> 5;
    int lane = threadIdx.x & 31;
    if (w >= Bn) return;
    int ip = __ldg(&pp[w]);
    int im = __ldg(&pm[w]);
    int it = __ldg(&map[__ldg(&pt[w])]);
    const float4* rp = (const float4*)(cp + (size_t)ip * HID);
    const float4* rm = (const float4*)(cm + (size_t)im * HID);
    const float4* rt = (const float4*)(ctc + (size_t)it * HID);
    const float4* rw = (const float4*)w2;
    float sum = 0.f;
#pragma unroll
    for (int v = 0; v < 2; v++) {
        float4 a = __ldg(&rp[lane + v * 32]);
        float4 b = __ldg(&rm[lane + v * 32]);
        float4 c = __ldg(&rt[lane + v * 32]);
        float4 ww = __ldg(&rw[lane + v * 32]);
        sum = fmaf(fmaxf(a.x + b.x + c.x, 0.f), ww.x, sum);
        sum = fmaf(fmaxf(a.y + b.y + c.y, 0.f), ww.y, sum);
        sum = fmaf(fmaxf(a.z + b.z + c.z, 0.f), ww.z, sum);
        sum = fmaf(fmaxf(a.w + b.w + c.w, 0.f), ww.w, sum);
    }
#pragma unroll
    for (int o = 16; o > 0; o >>= 1) sum += __shfl_xor_sync(0xFFFFFFFFu, sum, o);
    if (lane == 0) out[w] = sum + b2[0];
}

// ---------------- launch ----------------
static void launch_gemm(const float* A, int Ka, const float* Wa, int ldwa, int offa,
                        const float* B, int Kb, const float* Wb, int ldwb, int offb,
                        const float* bias, const int* rowidx_a, const int* rowidx_b,
                        const int* rows_ptr, float* Y, int rows, int relu) {
    dim3 grid(divup(rows, 128), HID / 128);
    gemm_kernel<<<grid, 256>>>(A, Ka, Wa, ldwa, offa, B, Kb, Wb, ldwb, offb, bias,
                               rowidx_a, rowidx_b, rows_ptr, Y, rows, HID, relu);
}

extern "C" void kernel_launch(void* const* d_in, const int* in_sizes, int n_in,
                              void* d_out, int out_size) {
    const float* emb_pep = (const float*)d_in[0];
    const float* emb_mhc = (const float*)d_in[1];
    const float* emb_tcr = (const float*)d_in[2];
    const int* src_pm = (const int*)d_in[3];
    const int* dst_pm = (const int*)d_in[4];
    const int* src_mt = (const int*)d_in[5];
    const int* dst_mt = (const int*)d_in[6];
    const int* pack_pep = (const int*)d_in[7];
    const int* pack_mhc = (const int*)d_in[8];
    const int* pack_tcr = (const int*)d_in[9];
    const float* l1_pm_Wl = (const float*)d_in[10];
    const float* l1_pm_bl = (const float*)d_in[11];
    const float* l1_pm_Wr = (const float*)d_in[12];
    const float* l1_mt_Wl = (const float*)d_in[13];
    const float* l1_mt_bl = (const float*)d_in[14];
    const float* l1_mt_Wr = (const float*)d_in[15];
    const float* l2_pm_Wl = (const float*)d_in[16];
    const float* l2_pm_bl = (const float*)d_in[17];
    const float* l2_pm_Wr = (const float*)d_in[18];
    const float* l2_mt_Wl = (const float*)d_in[19];
    const float* l2_mt_bl = (const float*)d_in[20];
    const float* l2_mt_Wr = (const float*)d_in[21];
    const float* proj_W = (const float*)d_in[22];
    const float* proj_b = (const float*)d_in[23];
    const float* head_W1 = (const float*)d_in[24];
    const float* head_b1 = (const float*)d_in[25];
    const float* head_W2 = (const float*)d_in[26];
    const float* head_b2 = (const float*)d_in[27];
    float* out = (float*)d_out;

    float *mean_pm, *mhc1, *mhc2, *cm, *cp, *Mp, *bp;
    float *mean_mt1c, *mean_mt2c, *tcr1c, *tcr2c, *ctc;
    int *map, *list, *cnt, *head_pm, *next_pm, *head_mt, *next_mt;
    cudaGetSymbolAddress((void**)&mean_pm, g_mean_pm);
    cudaGetSymbolAddress((void**)&mhc1, g_mhc1);
    cudaGetSymbolAddress((void**)&mhc2, g_mhc2);
    cudaGetSymbolAddress((void**)&cm, g_cm);
    cudaGetSymbolAddress((void**)&cp, g_cp);
    cudaGetSymbolAddress((void**)&Mp, g_Mp);
    cudaGetSymbolAddress((void**)&bp, g_bp);
    cudaGetSymbolAddress((void**)&mean_mt1c, g_mean_mt1c);
    cudaGetSymbolAddress((void**)&mean_mt2c, g_mean_mt2c);
    cudaGetSymbolAddress((void**)&tcr1c, g_tcr1c);
    cudaGetSymbolAddress((void**)&tcr2c, g_tcr2c);
    cudaGetSymbolAddress((void**)&ctc, g_ctc);
    cudaGetSymbolAddress((void**)&map, g_map);
    cudaGetSymbolAddress((void**)&list, g_list);
    cudaGetSymbolAddress((void**)&cnt, g_cnt);
    cudaGetSymbolAddress((void**)&head_pm, g_head_pm);
    cudaGetSymbolAddress((void**)&next_pm, g_next_pm);
    cudaGetSymbolAddress((void**)&head_mt, g_head_mt);
    cudaGetSymbolAddress((void**)&next_mt, g_next_mt);

    // 1) init + edge lists + dedup
    init_kernel<<<divup(N_TCR, 256), 256>>>(head_pm, head_mt, map, cnt);
    build_edges_kernel<<<divup(E_PM, 256), 256>>>(dst_pm, head_pm, next_pm, E_PM);
    build_edges_kernel<<<divup(E_MT, 256), 256>>>(dst_mt, head_mt, next_mt, E_MT);
    mark_kernel<<<divup(BATCH, 256), 256>>>(pack_tcr, map, BATCH);
    compact_kernel<<<divup(N_TCR, 256), 256>>>(map, list, cnt);

    // 2) layer-1 aggregations (mean_pm reused by layer 2; mt aggregation only on needed nodes)
    agg_kernel<EMB><<<divup(N_MHC, 8), 256>>>(head_pm, next_pm, src_pm, emb_pep, mean_pm, N_MHC);
    agg_compact_kernel<EMB><<<divup(MAXD, 8), 256>>>(head_mt, next_mt, src_mt, emb_mhc,
                                                     mean_mt1c, list, cnt);

    // 3) layer-1 SAGE GEMMs
    launch_gemm(mean_pm, EMB, l1_pm_Wl, EMB, 0, emb_mhc, EMB, l1_pm_Wr, EMB, 0,
                l1_pm_bl, nullptr, nullptr, nullptr, mhc1, N_MHC, 1);
    launch_gemm(mean_mt1c, EMB, l1_mt_Wl, EMB, 0, emb_tcr, EMB, l1_mt_Wr, EMB, 0,
                l1_mt_bl, nullptr, list, cnt, tcr1c, MAXD, 1);

    // 4) layer-2 aggregation over mhc1 (compacted)
    agg_compact_kernel<HID><<<divup(MAXD, 8), 256>>>(head_mt, next_mt, src_mt, mhc1,
                                                     mean_mt2c, list, cnt);

    // 5) layer-2 SAGE GEMMs
    launch_gemm(mean_pm, EMB, l2_pm_Wl, EMB, 0, mhc1, HID, l2_pm_Wr, HID, 0,
                l2_pm_bl, nullptr, nullptr, nullptr, mhc2, N_MHC, 1);
    launch_gemm(mean_mt2c, HID, l2_mt_Wl, HID, 0, tcr1c, HID, l2_mt_Wr, HID, 0,
                l2_mt_bl, nullptr, nullptr, cnt, tcr2c, MAXD, 1);

    // 6) head contributions
    prep_head_kernel<<<HID, 128>>>(head_W1, head_b1, proj_W, proj_b, Mp, bp);
    launch_gemm(emb_pep, EMB, Mp, EMB, 0, nullptr, 0, nullptr, 0, 0,
                bp, nullptr, nullptr, nullptr, cp, N_PEP, 0);
    launch_gemm(mhc2, HID, head_W1, 3 * HID, HID, nullptr, 0, nullptr, 0, 0,
                nullptr, nullptr, nullptr, nullptr, cm, N_MHC, 0);
    launch_gemm(tcr2c, HID, head_W1, 3 * HID, 2 * HID, nullptr, 0, nullptr, 0, 0,
                nullptr, nullptr, nullptr, cnt, ctc, MAXD, 0);

    // 7) final dot
    final_kernel<<<divup(BATCH, 8), 256>>>(pack_pep, pack_mhc, pack_tcr, map, cp, cm, ctc,
                                           head_W2, head_b2, out, BATCH);
}